// round 1
// baseline (speedup 1.0000x reference)
#include <cuda_runtime.h>
#include <cuda_bf16.h>

// Problem constants (fixed by the reference)
#define B_SEG   16
#define D_F     128   // fine feature dim
#define D_C     256   // coarse feature dim
#define D_OUT   (D_C + D_F)   // 384

// ---------------------------------------------------------------------------
// Zero the output (it is poisoned to 0xAA by the harness)
// ---------------------------------------------------------------------------
__global__ void zero_out_kernel(float* __restrict__ out, int n) {
    int i = blockIdx.x * blockDim.x + threadIdx.x;
    if (i < n) out[i] = 0.0f;
}

// ---------------------------------------------------------------------------
// Segment-sum for the FINE tensor: D=128 floats = 32 float4 per row.
// blockDim = 256: tid&31 -> float4 column, tid>>5 -> row lane (8 parallel rows).
// grid = (ceil(N_F / ROWS_F), B). Blocks beyond the segment end exit.
// Partial sums are tree-reduced in smem, then one atomicAdd per float.
// ---------------------------------------------------------------------------
#define ROWS_F 1024

__global__ void sum_fine_kernel(const float4* __restrict__ feats,
                                const int* __restrict__ lengths,
                                float* __restrict__ out) {
    const int b = blockIdx.y;
    int start = 0;
#pragma unroll
    for (int i = 0; i < B_SEG; ++i) {
        int li = lengths[i];
        if (i < b) start += li;
    }
    const int len = lengths[b];

    const int r0 = blockIdx.x * ROWS_F;
    if (r0 >= len) return;
    const int r1 = (r0 + ROWS_F < len) ? (r0 + ROWS_F) : len;

    const int c  = threadIdx.x & 31;   // float4 column 0..31
    const int rr = threadIdx.x >> 5;   // row lane 0..7

    float4 acc = make_float4(0.f, 0.f, 0.f, 0.f);
    const float4* base = feats + (long long)start * 32 + c;
#pragma unroll 4
    for (int r = r0 + rr; r < r1; r += 8) {
        float4 v = base[(long long)r * 32];
        acc.x += v.x; acc.y += v.y; acc.z += v.z; acc.w += v.w;
    }

    __shared__ float4 sh[256];
    sh[threadIdx.x] = acc;
    __syncthreads();

    if (rr == 0) {
        float4 s = sh[c];
#pragma unroll
        for (int k = 1; k < 8; ++k) {
            float4 v = sh[k * 32 + c];
            s.x += v.x; s.y += v.y; s.z += v.z; s.w += v.w;
        }
        float* o = out + (long long)b * D_OUT + D_C + c * 4;
        atomicAdd(o + 0, s.x);
        atomicAdd(o + 1, s.y);
        atomicAdd(o + 2, s.z);
        atomicAdd(o + 3, s.w);
    }
}

// ---------------------------------------------------------------------------
// Segment-sum for the COARSE tensor: D=256 floats = 64 float4 per row.
// blockDim = 256: tid&63 -> float4 column, tid>>6 -> row lane (4 parallel rows).
// ---------------------------------------------------------------------------
#define ROWS_C 512

__global__ void sum_coarse_kernel(const float4* __restrict__ feats,
                                  const int* __restrict__ lengths,
                                  float* __restrict__ out) {
    const int b = blockIdx.y;
    int start = 0;
#pragma unroll
    for (int i = 0; i < B_SEG; ++i) {
        int li = lengths[i];
        if (i < b) start += li;
    }
    const int len = lengths[b];

    const int r0 = blockIdx.x * ROWS_C;
    if (r0 >= len) return;
    const int r1 = (r0 + ROWS_C < len) ? (r0 + ROWS_C) : len;

    const int c  = threadIdx.x & 63;   // float4 column 0..63
    const int rr = threadIdx.x >> 6;   // row lane 0..3

    float4 acc = make_float4(0.f, 0.f, 0.f, 0.f);
    const float4* base = feats + (long long)start * 64 + c;
#pragma unroll 4
    for (int r = r0 + rr; r < r1; r += 4) {
        float4 v = base[(long long)r * 64];
        acc.x += v.x; acc.y += v.y; acc.z += v.z; acc.w += v.w;
    }

    __shared__ float4 sh[256];
    sh[threadIdx.x] = acc;
    __syncthreads();

    if (rr == 0) {
        float4 s = sh[c];
#pragma unroll
        for (int k = 1; k < 4; ++k) {
            float4 v = sh[k * 64 + c];
            s.x += v.x; s.y += v.y; s.z += v.z; s.w += v.w;
        }
        float* o = out + (long long)b * D_OUT + c * 4;
        atomicAdd(o + 0, s.x);
        atomicAdd(o + 1, s.y);
        atomicAdd(o + 2, s.z);
        atomicAdd(o + 3, s.w);
    }
}

// ---------------------------------------------------------------------------
// Divide sums by segment lengths (coarse cols use lengths_c, fine use lengths_f)
// ---------------------------------------------------------------------------
__global__ void finalize_kernel(float* __restrict__ out,
                                const int* __restrict__ lengths_f,
                                const int* __restrict__ lengths_c) {
    int i = blockIdx.x * blockDim.x + threadIdx.x;
    if (i >= B_SEG * D_OUT) return;
    int b = i / D_OUT;
    int d = i - b * D_OUT;
    int len = (d < D_C) ? lengths_c[b] : lengths_f[b];
    out[i] = out[i] / (float)len;
}

// ---------------------------------------------------------------------------
extern "C" void kernel_launch(void* const* d_in, const int* in_sizes, int n_in,
                              void* d_out, int out_size) {
    const float* feats_f   = (const float*)d_in[0];   // [524288, 128]
    const float* feats_c   = (const float*)d_in[1];   // [32768, 256]
    const int*   lengths_f = (const int*)d_in[2];     // [16]
    const int*   lengths_c = (const int*)d_in[3];     // [16]
    float* out = (float*)d_out;                       // [16, 384]

    const int n_f = in_sizes[0] / D_F;   // total fine rows
    const int n_c = in_sizes[1] / D_C;   // total coarse rows
    const int n_out = B_SEG * D_OUT;     // 6144

    zero_out_kernel<<<(n_out + 255) / 256, 256>>>(out, n_out);

    dim3 gc((n_c + ROWS_C - 1) / ROWS_C, B_SEG);
    sum_coarse_kernel<<<gc, 256>>>((const float4*)feats_c, lengths_c, out);

    dim3 gf((n_f + ROWS_F - 1) / ROWS_F, B_SEG);
    sum_fine_kernel<<<gf, 256>>>((const float4*)feats_f, lengths_f, out);

    finalize_kernel<<<(n_out + 255) / 256, 256>>>(out, lengths_f, lengths_c);
}

// round 2
// speedup vs baseline: 1.1757x; 1.1757x over previous
#include <cuda_runtime.h>
#include <cuda_bf16.h>

// Problem constants (fixed by the reference)
#define B_SEG   16
#define D_F     128            // fine feature dim  (32 float4)
#define D_C     256            // coarse feature dim (64 float4)
#define D_OUT   (D_C + D_F)    // 384

#define ROWS_C  512            // coarse rows per block  -> 64 blocks
#define ROWS_F  1024           // fine rows per block    -> 512 blocks
#define NBLK_C  64             // 32768 / 512
#define NBLK_F  512            // 524288 / 1024

// Self-restoring scratch accumulator: zero-initialized at module load;
// the finalize kernel resets it to zero after reading, so every call of
// kernel_launch sees it zeroed (deterministic across graph replays).
__device__ float g_scratch[B_SEG * D_OUT];

// ---------------------------------------------------------------------------
// Fused segment-sum over both tensors.
// blockIdx.x < NBLK_C  -> coarse tile, else fine tile.
// Each block owns a GLOBAL row range and walks segment boundaries via the
// cumsum of lengths (block-uniform control flow), so no CTA is wasted.
// ---------------------------------------------------------------------------
__global__ __launch_bounds__(256)
void sum_fused_kernel(const float4* __restrict__ feats_c,
                      const float4* __restrict__ feats_f,
                      const int* __restrict__ lengths_c,
                      const int* __restrict__ lengths_f,
                      int n_c, int n_f) {
    __shared__ float4 sh[256];
    const int tid = threadIdx.x;

    if (blockIdx.x < NBLK_C) {
        // ---------------- coarse: 64 float4 cols, 4 row lanes ----------------
        const int c  = tid & 63;
        const int rr = tid >> 6;

        int cum[B_SEG + 1];
        cum[0] = 0;
#pragma unroll
        for (int i = 0; i < B_SEG; ++i) cum[i + 1] = cum[i] + lengths_c[i];

        int r0 = blockIdx.x * ROWS_C;
        int r1 = r0 + ROWS_C; if (r1 > n_c) r1 = n_c;
        if (r0 >= r1) return;

        int s = 0;
        while (cum[s + 1] <= r0) ++s;

        while (r0 < r1) {
            int e = cum[s + 1]; if (e > r1) e = r1;

            float4 acc = make_float4(0.f, 0.f, 0.f, 0.f);
            const float4* base = feats_c + c;
#pragma unroll 4
            for (int r = r0 + rr; r < e; r += 4) {
                float4 v = base[(long long)r * 64];
                acc.x += v.x; acc.y += v.y; acc.z += v.z; acc.w += v.w;
            }

            sh[tid] = acc;
            __syncthreads();
            if (rr == 0) {
                float4 t = sh[c];
#pragma unroll
                for (int k = 1; k < 4; ++k) {
                    float4 v = sh[k * 64 + c];
                    t.x += v.x; t.y += v.y; t.z += v.z; t.w += v.w;
                }
                float* o = g_scratch + s * D_OUT + c * 4;
                atomicAdd(o + 0, t.x);
                atomicAdd(o + 1, t.y);
                atomicAdd(o + 2, t.z);
                atomicAdd(o + 3, t.w);
            }
            __syncthreads();
            r0 = e; ++s;
        }
    } else {
        // ---------------- fine: 32 float4 cols, 8 row lanes ------------------
        const int c  = tid & 31;
        const int rr = tid >> 5;

        int cum[B_SEG + 1];
        cum[0] = 0;
#pragma unroll
        for (int i = 0; i < B_SEG; ++i) cum[i + 1] = cum[i] + lengths_f[i];

        int r0 = (blockIdx.x - NBLK_C) * ROWS_F;
        int r1 = r0 + ROWS_F; if (r1 > n_f) r1 = n_f;
        if (r0 >= r1) return;

        int s = 0;
        while (cum[s + 1] <= r0) ++s;

        while (r0 < r1) {
            int e = cum[s + 1]; if (e > r1) e = r1;

            float4 acc = make_float4(0.f, 0.f, 0.f, 0.f);
            const float4* base = feats_f + c;
#pragma unroll 4
            for (int r = r0 + rr; r < e; r += 8) {
                float4 v = base[(long long)r * 32];
                acc.x += v.x; acc.y += v.y; acc.z += v.z; acc.w += v.w;
            }

            sh[tid] = acc;
            __syncthreads();
            if (rr == 0) {
                float4 t = sh[c];
#pragma unroll
                for (int k = 1; k < 8; ++k) {
                    float4 v = sh[k * 32 + c];
                    t.x += v.x; t.y += v.y; t.z += v.z; t.w += v.w;
                }
                float* o = g_scratch + s * D_OUT + D_C + c * 4;
                atomicAdd(o + 0, t.x);
                atomicAdd(o + 1, t.y);
                atomicAdd(o + 2, t.z);
                atomicAdd(o + 3, t.w);
            }
            __syncthreads();
            r0 = e; ++s;
        }
    }
}

// ---------------------------------------------------------------------------
// out = scratch / len ; scratch = 0  (restores the invariant for next replay)
// ---------------------------------------------------------------------------
__global__ void finalize_kernel(float* __restrict__ out,
                                const int* __restrict__ lengths_f,
                                const int* __restrict__ lengths_c) {
    int i = blockIdx.x * blockDim.x + threadIdx.x;
    if (i >= B_SEG * D_OUT) return;
    int b = i / D_OUT;
    int d = i - b * D_OUT;
    int len = (d < D_C) ? lengths_c[b] : lengths_f[b];
    out[i] = g_scratch[i] / (float)len;
    g_scratch[i] = 0.0f;
}

// ---------------------------------------------------------------------------
extern "C" void kernel_launch(void* const* d_in, const int* in_sizes, int n_in,
                              void* d_out, int out_size) {
    const float* feats_f   = (const float*)d_in[0];   // [524288, 128]
    const float* feats_c   = (const float*)d_in[1];   // [32768, 256]
    const int*   lengths_f = (const int*)d_in[2];     // [16]
    const int*   lengths_c = (const int*)d_in[3];     // [16]
    float* out = (float*)d_out;                       // [16, 384]

    const int n_f = in_sizes[0] / D_F;   // total fine rows
    const int n_c = in_sizes[1] / D_C;   // total coarse rows
    const int n_out = B_SEG * D_OUT;     // 6144

    const int nblk = NBLK_C + (n_f + ROWS_F - 1) / ROWS_F;
    sum_fused_kernel<<<nblk, 256>>>((const float4*)feats_c,
                                    (const float4*)feats_f,
                                    lengths_c, lengths_f, n_c, n_f);

    finalize_kernel<<<(n_out + 255) / 256, 256>>>(out, lengths_f, lengths_c);
}

// round 4
// speedup vs baseline: 1.2120x; 1.0308x over previous
#include <cuda_runtime.h>
#include <cuda_bf16.h>

// Problem constants (fixed by the reference)
#define B_SEG   16
#define D_F     128            // fine feature dim  (32 float4)
#define D_C     256            // coarse feature dim (64 float4)
#define D_OUT   (D_C + D_F)    // 384

#define ROWS_C  256            // coarse rows per tile  -> 128 tiles
#define ROWS_F  512            // fine rows per tile    -> 1024 tiles
#define NBLK_C  128            // 32768 / 256

// Self-restoring device state: zero-initialized at module load; the
// last-block finalize resets everything, so every graph replay sees the
// same initial state (deterministic).
__device__ float        g_scratch[B_SEG * D_OUT];
__device__ unsigned int g_count;

// ---------------------------------------------------------------------------
// Single fused kernel: segment-sum over both tensors + last-block finalize.
// blockIdx.x < NBLK_C -> coarse tile, else fine tile. Each block owns a
// GLOBAL row range and walks segment boundaries via a smem cumsum.
// ---------------------------------------------------------------------------
__global__ __launch_bounds__(256, 8)
void pare_fused_kernel(const float4* __restrict__ feats_c,
                       const float4* __restrict__ feats_f,
                       const int* __restrict__ lengths_c,
                       const int* __restrict__ lengths_f,
                       float* __restrict__ out,
                       int n_c, int n_f) {
    __shared__ float4 sh[256];
    __shared__ int    scum[B_SEG + 1];
    __shared__ bool   sdone;
    const int tid = threadIdx.x;

    const bool is_c = (blockIdx.x < NBLK_C);

    // cumsum of the relevant lengths, in smem (keeps registers low)
    if (tid == 0) {
        const int* L = is_c ? lengths_c : lengths_f;
        int acc = 0;
        scum[0] = 0;
#pragma unroll
        for (int i = 0; i < B_SEG; ++i) { acc += L[i]; scum[i + 1] = acc; }
    }
    __syncthreads();

    if (is_c) {
        // ------------- coarse: 64 float4 cols, 4 row lanes -------------
        const int c  = tid & 63;
        const int rr = tid >> 6;

        int r0 = blockIdx.x * ROWS_C;
        int r1 = r0 + ROWS_C; if (r1 > n_c) r1 = n_c;

        int s = 0;
        while (scum[s + 1] <= r0) ++s;

        while (r0 < r1) {
            int e = scum[s + 1]; if (e > r1) e = r1;

            float4 acc = make_float4(0.f, 0.f, 0.f, 0.f);
            const float4* base = feats_c + c;
#pragma unroll 4
            for (int r = r0 + rr; r < e; r += 4) {
                float4 v = base[(long long)r * 64];
                acc.x += v.x; acc.y += v.y; acc.z += v.z; acc.w += v.w;
            }

            sh[tid] = acc;
            __syncthreads();
            if (rr == 0) {
                float4 t = sh[c];
#pragma unroll
                for (int k = 1; k < 4; ++k) {
                    float4 v = sh[k * 64 + c];
                    t.x += v.x; t.y += v.y; t.z += v.z; t.w += v.w;
                }
                float* o = g_scratch + s * D_OUT + c * 4;
                atomicAdd(o + 0, t.x);
                atomicAdd(o + 1, t.y);
                atomicAdd(o + 2, t.z);
                atomicAdd(o + 3, t.w);
            }
            __syncthreads();
            r0 = e; ++s;
        }
    } else {
        // ------------- fine: 32 float4 cols, 8 row lanes ---------------
        const int c  = tid & 31;
        const int rr = tid >> 5;

        int r0 = (blockIdx.x - NBLK_C) * ROWS_F;
        int r1 = r0 + ROWS_F; if (r1 > n_f) r1 = n_f;

        int s = 0;
        while (scum[s + 1] <= r0) ++s;

        while (r0 < r1) {
            int e = scum[s + 1]; if (e > r1) e = r1;

            float4 acc = make_float4(0.f, 0.f, 0.f, 0.f);
            const float4* base = feats_f + c;
#pragma unroll 4
            for (int r = r0 + rr; r < e; r += 8) {
                float4 v = base[(long long)r * 32];
                acc.x += v.x; acc.y += v.y; acc.z += v.z; acc.w += v.w;
            }

            sh[tid] = acc;
            __syncthreads();
            if (rr == 0) {
                float4 t = sh[c];
#pragma unroll
                for (int k = 1; k < 8; ++k) {
                    float4 v = sh[k * 32 + c];
                    t.x += v.x; t.y += v.y; t.z += v.z; t.w += v.w;
                }
                float* o = g_scratch + s * D_OUT + D_C + c * 4;
                atomicAdd(o + 0, t.x);
                atomicAdd(o + 1, t.y);
                atomicAdd(o + 2, t.z);
                atomicAdd(o + 3, t.w);
            }
            __syncthreads();
            r0 = e; ++s;
        }
    }

    // ---- last block to finish performs finalize + state reset ----
    if (tid == 0) {
        __threadfence();
        unsigned int old = atomicAdd(&g_count, 1u);
        sdone = (old == gridDim.x - 1);
    }
    __syncthreads();

    if (sdone) {
        __threadfence();  // make all blocks' atomics visible to this block
        for (int i = tid; i < B_SEG * D_OUT; i += 256) {
            int b = i / D_OUT;
            int d = i - b * D_OUT;
            int len = (d < D_C) ? lengths_c[b] : lengths_f[b];
            out[i] = g_scratch[i] / (float)len;
            g_scratch[i] = 0.0f;
        }
        __syncthreads();
        if (tid == 0) g_count = 0u;
    }
}

// ---------------------------------------------------------------------------
extern "C" void kernel_launch(void* const* d_in, const int* in_sizes, int n_in,
                              void* d_out, int out_size) {
    const float* feats_f   = (const float*)d_in[0];   // [524288, 128]
    const float* feats_c   = (const float*)d_in[1];   // [32768, 256]
    const int*   lengths_f = (const int*)d_in[2];     // [16]
    const int*   lengths_c = (const int*)d_in[3];     // [16]
    float* out = (float*)d_out;                       // [16, 384]

    const int n_f = in_sizes[0] / D_F;   // total fine rows
    const int n_c = in_sizes[1] / D_C;   // total coarse rows

    const int nblk = NBLK_C + (n_f + ROWS_F - 1) / ROWS_F;  // 1152
    pare_fused_kernel<<<nblk, 256>>>((const float4*)feats_c,
                                     (const float4*)feats_f,
                                     lengths_c, lengths_f, out, n_c, n_f);
}

// round 7
// speedup vs baseline: 1.2180x; 1.0050x over previous
#include <cuda_runtime.h>
#include <cuda_bf16.h>

// Problem constants (fixed by the reference)
#define B_SEG   16
#define D_F     128            // fine feature dim  (32 float4)
#define D_C     256            // coarse feature dim (64 float4)
#define D_OUT   (D_C + D_F)    // 384

// Exactly one full wave on 148 SMs at occupancy 8: 148*8 = 1184 CTAs.
// Tiles sized for equal bytes: coarse tile ~248KB, fine tile ~249KB.
#define NT_C    132            // coarse tiles
#define NT_F    1052           // fine tiles
#define NBLK    (NT_C + NT_F)  // 1184

// Self-restoring device state: zero-initialized at module load; the
// last-block finalize resets everything, so every graph replay sees the
// same initial state (deterministic).
__device__ float        g_scratch[B_SEG * D_OUT];
__device__ unsigned int g_count;

// ---------------------------------------------------------------------------
// Single fused kernel: segment-sum over both tensors + last-block finalize.
// blockIdx.x < NT_C -> coarse tile, else fine tile. Each block owns a
// GLOBAL row range computed as [t*n/NT, (t+1)*n/NT) and walks segment
// boundaries via a smem cumsum.
// ---------------------------------------------------------------------------
__global__ __launch_bounds__(256, 8)
void pare_fused_kernel(const float4* __restrict__ feats_c,
                       const float4* __restrict__ feats_f,
                       const int* __restrict__ lengths_c,
                       const int* __restrict__ lengths_f,
                       float* __restrict__ out,
                       int n_c, int n_f) {
    __shared__ float4 sh[256];
    __shared__ int    scum[B_SEG + 1];
    __shared__ bool   sdone;
    const int tid = threadIdx.x;

    const bool is_c = (blockIdx.x < NT_C);

    // cumsum of the relevant lengths, in smem (keeps registers low)
    if (tid == 0) {
        const int* L = is_c ? lengths_c : lengths_f;
        int acc = 0;
        scum[0] = 0;
#pragma unroll
        for (int i = 0; i < B_SEG; ++i) { acc += L[i]; scum[i + 1] = acc; }
    }
    __syncthreads();

    if (is_c) {
        // ------------- coarse: 64 float4 cols, 4 row lanes -------------
        const int c  = tid & 63;
        const int rr = tid >> 6;
        const int t  = blockIdx.x;

        int r0 = (int)(((long long)t)       * n_c / NT_C);
        int r1 = (int)(((long long)(t + 1)) * n_c / NT_C);

        int s = 0;
        while (scum[s + 1] <= r0) ++s;

        while (r0 < r1) {
            int e = scum[s + 1]; if (e > r1) e = r1;

            float4 acc = make_float4(0.f, 0.f, 0.f, 0.f);
            const float4* base = feats_c + c;
#pragma unroll 4
            for (int r = r0 + rr; r < e; r += 4) {
                float4 v = __ldcs(base + (long long)r * 64);
                acc.x += v.x; acc.y += v.y; acc.z += v.z; acc.w += v.w;
            }

            sh[tid] = acc;
            __syncthreads();
            if (rr == 0) {
                float4 v1 = sh[64 + c], v2 = sh[128 + c], v3 = sh[192 + c];
                float4 tt = sh[c];
                tt.x += v1.x + v2.x + v3.x;
                tt.y += v1.y + v2.y + v3.y;
                tt.z += v1.z + v2.z + v3.z;
                tt.w += v1.w + v2.w + v3.w;
                float* o = g_scratch + s * D_OUT + c * 4;
                atomicAdd(o + 0, tt.x);
                atomicAdd(o + 1, tt.y);
                atomicAdd(o + 2, tt.z);
                atomicAdd(o + 3, tt.w);
            }
            __syncthreads();
            r0 = e; ++s;
        }
    } else {
        // ------------- fine: 32 float4 cols, 8 row lanes ---------------
        const int c  = tid & 31;
        const int rr = tid >> 5;
        const int t  = blockIdx.x - NT_C;

        int r0 = (int)(((long long)t)       * n_f / NT_F);
        int r1 = (int)(((long long)(t + 1)) * n_f / NT_F);

        int s = 0;
        while (scum[s + 1] <= r0) ++s;

        while (r0 < r1) {
            int e = scum[s + 1]; if (e > r1) e = r1;

            float4 acc = make_float4(0.f, 0.f, 0.f, 0.f);
            const float4* base = feats_f + c;
#pragma unroll 4
            for (int r = r0 + rr; r < e; r += 8) {
                float4 v = __ldcs(base + (long long)r * 32);
                acc.x += v.x; acc.y += v.y; acc.z += v.z; acc.w += v.w;
            }

            sh[tid] = acc;
            __syncthreads();
            if (rr == 0) {
                float4 tt = sh[c];
#pragma unroll
                for (int k = 1; k < 8; ++k) {
                    float4 v = sh[k * 32 + c];
                    tt.x += v.x; tt.y += v.y; tt.z += v.z; tt.w += v.w;
                }
                float* o = g_scratch + s * D_OUT + D_C + c * 4;
                atomicAdd(o + 0, tt.x);
                atomicAdd(o + 1, tt.y);
                atomicAdd(o + 2, tt.z);
                atomicAdd(o + 3, tt.w);
            }
            __syncthreads();
            r0 = e; ++s;
        }
    }

    // ---- last block to finish performs finalize + state reset ----
    if (tid == 0) {
        __threadfence();
        unsigned int old = atomicAdd(&g_count, 1u);
        sdone = (old == gridDim.x - 1);
    }
    __syncthreads();

    if (sdone) {
        __threadfence();  // make all blocks' atomics visible to this block
        for (int i = tid; i < B_SEG * D_OUT; i += 256) {
            int b = i / D_OUT;
            int d = i - b * D_OUT;
            int len = (d < D_C) ? lengths_c[b] : lengths_f[b];
            out[i] = g_scratch[i] / (float)len;
            g_scratch[i] = 0.0f;
        }
        __syncthreads();
        if (tid == 0) g_count = 0u;
    }
}

// ---------------------------------------------------------------------------
extern "C" void kernel_launch(void* const* d_in, const int* in_sizes, int n_in,
                              void* d_out, int out_size) {
    const float* feats_f   = (const float*)d_in[0];   // [524288, 128]
    const float* feats_c   = (const float*)d_in[1];   // [32768, 256]
    const int*   lengths_f = (const int*)d_in[2];     // [16]
    const int*   lengths_c = (const int*)d_in[3];     // [16]
    float* out = (float*)d_out;                       // [16, 384]

    const int n_f = in_sizes[0] / D_F;   // total fine rows
    const int n_c = in_sizes[1] / D_C;   // total coarse rows

    pare_fused_kernel<<<NBLK, 256>>>((const float4*)feats_c,
                                     (const float4*)feats_f,
                                     lengths_c, lengths_f, out, n_c, n_f);
}